// round 11
// baseline (speedup 1.0000x reference)
#include <cuda_runtime.h>
#include <cuda_bf16.h>
#include <math.h>
#include <stdint.h>

#define NTOK   196
#define CDIM   768
#define BATCH  256
#define NCLS   701
#define NPAD   704      // NCLS padded to 64-multiple

// bf16 hi/lo pre-split operands (device scratch; no allocation)
__device__ __nv_bfloat16 g_Ah[4 * BATCH * CDIM];   // [1024][768]
__device__ __nv_bfloat16 g_Al[4 * BATCH * CDIM];
__device__ __nv_bfloat16 g_Wh[CDIM * NPAD];        // [768][704]
__device__ __nv_bfloat16 g_Wl[CDIM * NPAD];

__device__ __forceinline__ uint32_t smem_u32(const void* p) {
    uint32_t a;
    asm("{ .reg .u64 t; cvta.to.shared.u64 t, %1; cvt.u32.u64 %0, t; }"
        : "=r"(a) : "l"(p));
    return a;
}
__device__ __forceinline__ void split2(float f0, float f1,
                                       uint32_t& hi2, uint32_t& lo2) {
    __nv_bfloat16 h0 = __float2bfloat16(f0);
    __nv_bfloat16 h1 = __float2bfloat16(f1);
    __nv_bfloat16 l0 = __float2bfloat16(f0 - __bfloat162float(h0));
    __nv_bfloat16 l1 = __float2bfloat16(f1 - __bfloat162float(h1));
    __nv_bfloat162 h = __halves2bfloat162(h0, h1);
    __nv_bfloat162 l = __halves2bfloat162(l0, l1);
    hi2 = *reinterpret_cast<uint32_t*>(&h);
    lo2 = *reinterpret_cast<uint32_t*>(&l);
}

// ============================================================================
// Kernel 1: fused SGM per (tensor, sample)  [gridDim.y == 0,1]
//           + W hi/lo split                 [gridDim.y == 2]
// (R9 version — measured ~61us)
// ============================================================================
__global__ void __launch_bounds__(256)
sgm_kernel(const float* __restrict__ x1, const float* __restrict__ x2,
           const float* __restrict__ W) {
    const int tid  = threadIdx.x;

    if (blockIdx.y == 2) {
        const int tot = CDIM * NPAD;
        for (int idx = blockIdx.x * 256 + tid; idx < tot; idx += BATCH * 256) {
            int k = idx / NPAD;
            int n = idx - k * NPAD;
            float v = (n < NCLS) ? W[(size_t)k * NCLS + n] : 0.f;
            __nv_bfloat16 h = __float2bfloat16(v);
            g_Wh[idx] = h;
            g_Wl[idx] = __float2bfloat16(v - __bfloat162float(h));
        }
        return;
    }

    const int b      = blockIdx.x;
    const int tensor = blockIdx.y;
    const float* x = (tensor == 0 ? x1 : x2) + (size_t)b * NTOK * CDIM;

    __shared__ float sT[8][CDIM];
    __shared__ float sTtot[CDIM];
    __shared__ float sM[NTOK];
    __shared__ float sSorted[NTOK];
    __shared__ float sVal[256];
    __shared__ float sMax[256];
    __shared__ int   sIdx[256];
    __shared__ int   sList[112];
    __shared__ int   sCnt;
    __shared__ float sMnMx[2];

    const int warp = tid >> 5;
    const int lane = tid & 31;

    float tacc[24];
#pragma unroll
    for (int i = 0; i < 24; i++) tacc[i] = 0.f;

    int n = warp;
    for (; n + 8 < NTOK; n += 16) {
        const float4* rowA = reinterpret_cast<const float4*>(x + (size_t)n * CDIM);
        const float4* rowB = reinterpret_cast<const float4*>(x + (size_t)(n + 8) * CDIM);
        float msA = 0.f, msB = 0.f;
#pragma unroll
        for (int i = 0; i < 6; i++) {
            float4 va = rowA[lane + 32 * i];
            float4 vb = rowB[lane + 32 * i];
            tacc[4*i+0] += va.x + vb.x; tacc[4*i+1] += va.y + vb.y;
            tacc[4*i+2] += va.z + vb.z; tacc[4*i+3] += va.w + vb.w;
            msA += (va.x + va.y) + (va.z + va.w);
            msB += (vb.x + vb.y) + (vb.z + vb.w);
        }
#pragma unroll
        for (int off = 16; off > 0; off >>= 1) {
            msA += __shfl_down_sync(0xffffffffu, msA, off);
            msB += __shfl_down_sync(0xffffffffu, msB, off);
        }
        if (lane == 0) { sM[n] = msA; sM[n + 8] = msB; }
    }
    if (n < NTOK) {
        const float4* row = reinterpret_cast<const float4*>(x + (size_t)n * CDIM);
        float msum = 0.f;
#pragma unroll
        for (int i = 0; i < 6; i++) {
            float4 v = row[lane + 32 * i];
            tacc[4*i+0] += v.x; tacc[4*i+1] += v.y;
            tacc[4*i+2] += v.z; tacc[4*i+3] += v.w;
            msum += (v.x + v.y) + (v.z + v.w);
        }
#pragma unroll
        for (int off = 16; off > 0; off >>= 1)
            msum += __shfl_down_sync(0xffffffffu, msum, off);
        if (lane == 0) sM[n] = msum;
    }
    {
        float4* st = reinterpret_cast<float4*>(&sT[warp][0]);
#pragma unroll
        for (int i = 0; i < 6; i++)
            st[lane + 32 * i] = make_float4(tacc[4*i], tacc[4*i+1], tacc[4*i+2], tacc[4*i+3]);
    }
    if (tid == 0) sCnt = 0;
    __syncthreads();

    if (tid < 192) {
        float4 t = make_float4(0.f, 0.f, 0.f, 0.f);
#pragma unroll
        for (int w = 0; w < 8; w++) {
            float4 v = reinterpret_cast<float4*>(&sT[w][0])[tid];
            t.x += v.x; t.y += v.y; t.z += v.z; t.w += v.w;
        }
        reinterpret_cast<float4*>(sTtot)[tid] = t;
    }
    __syncthreads();

    sVal[tid] = (tid < NTOK) ? sM[tid] : 3.4e38f;
    sMax[tid] = (tid < NTOK) ? sM[tid] : -3.4e38f;
    __syncthreads();
    for (int s = 128; s > 0; s >>= 1) {
        if (tid < s) {
            sVal[tid] = fminf(sVal[tid], sVal[tid + s]);
            sMax[tid] = fmaxf(sMax[tid], sMax[tid + s]);
        }
        __syncthreads();
    }
    if (tid == 0) { sMnMx[0] = sVal[0]; sMnMx[1] = sMax[0]; }
    __syncthreads();

    const float mn  = sMnMx[0];
    const float mx  = sMnMx[1];
    const float inv = 1.f / (mx - mn);

    float myMn = 0.f;
    if (tid < NTOK) myMn = (sM[tid] - mn) * inv;
    sVal[tid] = myMn;
    __syncthreads();

    int myrank = 0;
    if (tid < NTOK) {
        int r = 0;
#pragma unroll 4
        for (int m = 0; m < NTOK; m++) {
            float o = sVal[m];
            r += (o < myMn) || (o == myMn && m < tid);
        }
        myrank = r;
        sSorted[r] = myMn;
    }
    __syncthreads();

    float dv = -1.f;
    if (tid < NTOK - 1) {
        float s0 = sSorted[tid];
        dv = (s0 == 0.f) ? 0.f : (sSorted[tid + 1] - s0);
    }
    sVal[tid] = dv;
    sIdx[tid] = tid;
    __syncthreads();
    for (int s = 128; s > 0; s >>= 1) {
        if (tid < s) {
            float v2 = sVal[tid + s]; int i2 = sIdx[tid + s];
            if (v2 > sVal[tid] || (v2 == sVal[tid] && i2 < sIdx[tid])) {
                sVal[tid] = v2; sIdx[tid] = i2;
            }
        }
        __syncthreads();
    }
    const int  k         = sIdx[0];
    const bool smallIsFg = (k <= NTOK / 2);

    if (tid < NTOK) {
        bool inSmall = smallIsFg ? (myrank < k) : (myrank >= k);
        if (inSmall) {
            int p = atomicAdd(&sCnt, 1);
            sList[p] = tid;
        }
    }
    __syncthreads();
    const int cnt = sCnt;

#pragma unroll
    for (int i = 0; i < 24; i++) tacc[i] = 0.f;
    for (int j = warp; j < cnt; j += 8) {
        int nn = sList[j];
        const float4* row = reinterpret_cast<const float4*>(x + (size_t)nn * CDIM);
#pragma unroll
        for (int i = 0; i < 6; i++) {
            float4 v = row[lane + 32 * i];
            tacc[4*i+0] += v.x; tacc[4*i+1] += v.y;
            tacc[4*i+2] += v.z; tacc[4*i+3] += v.w;
        }
    }
    {
        float4* st = reinterpret_cast<float4*>(&sT[warp][0]);
#pragma unroll
        for (int i = 0; i < 6; i++)
            st[lane + 32 * i] = make_float4(tacc[4*i], tacc[4*i+1], tacc[4*i+2], tacc[4*i+3]);
    }
    __syncthreads();

    if (tid < 192) {
        float4 S = make_float4(0.f, 0.f, 0.f, 0.f);
#pragma unroll
        for (int w = 0; w < 8; w++) {
            float4 v = reinterpret_cast<float4*>(&sT[w][0])[tid];
            S.x += v.x; S.y += v.y; S.z += v.z; S.w += v.w;
        }
        float4 T = reinterpret_cast<float4*>(sTtot)[tid];

        float4 fgs, bgs;
        if (smallIsFg) {
            fgs = S;
            bgs = make_float4(T.x - S.x, T.y - S.y, T.z - S.z, T.w - S.w);
        } else {
            bgs = S;
            fgs = make_float4(T.x - S.x, T.y - S.y, T.z - S.z, T.w - S.w);
        }
        const float fgc = fmaxf((float)k, 1.f);
        const float bgc = fmaxf((float)(NTOK - k), 1.f);
        float4 fg = make_float4(fgs.x / fgc, fgs.y / fgc, fgs.z / fgc, fgs.w / fgc);
        float4 bg = make_float4(bgs.x / bgc, bgs.y / bgc, bgs.z / bgc, bgs.w / bgc);

        const size_t rowBg = (size_t)((tensor * 2 + 0) * BATCH + b) * CDIM + tid * 4;
        const size_t rowFg = (size_t)((tensor * 2 + 1) * BATCH + b) * CDIM + tid * 4;
        uint32_t h01, l01, h23, l23;
        split2(bg.x, bg.y, h01, l01);
        split2(bg.z, bg.w, h23, l23);
        *reinterpret_cast<uint2*>(&g_Ah[rowBg]) = make_uint2(h01, h23);
        *reinterpret_cast<uint2*>(&g_Al[rowBg]) = make_uint2(l01, l23);
        split2(fg.x, fg.y, h01, l01);
        split2(fg.z, fg.w, h23, l23);
        *reinterpret_cast<uint2*>(&g_Ah[rowFg]) = make_uint2(h01, h23);
        *reinterpret_cast<uint2*>(&g_Al[rowFg]) = make_uint2(l01, l23);
    }
}

// ============================================================================
// Kernel 2: HMMA GEMM, tile 64x64, 512 threads = 16 warps (4x4 layout),
// warp tile 16x16, BK=64, cp.async double-buffered. Grid 11x16=176 blocks.
// ============================================================================
#define GBM 64
#define GBN 64
#define GBK 64
#define NTHR 512
#define PITCH 72
#define ROWB (PITCH * 2)         // 144 bytes per 64-element bf16 row
#define NSTAGE (CDIM / GBK)      // 12
#define OFF_AH 0                 // 64 rows * 144 = 9216
#define OFF_AL 9216
#define OFF_BH 18432
#define OFF_BL 27648
#define BUFSZ  36864
#define SMEM_TOTAL (2 * BUFSZ)   // 73728

__device__ __forceinline__ void cp16(uint32_t dst, const void* src) {
    asm volatile("cp.async.cg.shared.global [%0], [%1], 16;" :: "r"(dst), "l"(src));
}
__device__ __forceinline__ void ldm_x4(uint32_t r[4], uint32_t addr) {
    asm volatile("ldmatrix.sync.aligned.m8n8.x4.shared.b16 {%0,%1,%2,%3}, [%4];"
                 : "=r"(r[0]), "=r"(r[1]), "=r"(r[2]), "=r"(r[3]) : "r"(addr));
}
__device__ __forceinline__ void ldm_x4_t(uint32_t r[4], uint32_t addr) {
    asm volatile("ldmatrix.sync.aligned.m8n8.x4.trans.shared.b16 {%0,%1,%2,%3}, [%4];"
                 : "=r"(r[0]), "=r"(r[1]), "=r"(r[2]), "=r"(r[3]) : "r"(addr));
}
__device__ __forceinline__ void mma_bf16(float c[4], const uint32_t a[4],
                                         uint32_t b0, uint32_t b1) {
    asm volatile(
        "mma.sync.aligned.m16n8k16.row.col.f32.bf16.bf16.f32 "
        "{%0,%1,%2,%3}, {%4,%5,%6,%7}, {%8,%9}, {%0,%1,%2,%3};"
        : "+f"(c[0]), "+f"(c[1]), "+f"(c[2]), "+f"(c[3])
        : "r"(a[0]), "r"(a[1]), "r"(a[2]), "r"(a[3]), "r"(b0), "r"(b1));
}

__device__ __forceinline__ void issue_stage(uint32_t sbase, int buf, int s,
                                            int r0, int c0, int tid) {
    const int k0 = s * GBK;
    const uint32_t base = sbase + (uint32_t)buf * BUFSZ;
    // A: 64 rows x 8 chunks = 512 cp16 per array -> 1 per thread each
    {
        int m  = tid >> 3;               // 0..63
        int ch = tid & 7;
        uint32_t so = (uint32_t)(m * ROWB + ch * 16);
        const size_t aoff = (size_t)(r0 + m) * CDIM + k0 + ch * 8;
        cp16(base + OFF_AH + so, g_Ah + aoff);
        cp16(base + OFF_AL + so, g_Al + aoff);
    }
    // B: 64 k-rows x 8 chunks = 512 cp16 per array -> 1 per thread each
    {
        int kk = tid >> 3;               // 0..63
        int ch = tid & 7;
        uint32_t so = (uint32_t)(kk * ROWB + ch * 16);
        const size_t boff = (size_t)(k0 + kk) * NPAD + c0 + ch * 8;
        cp16(base + OFF_BH + so, g_Wh + boff);
        cp16(base + OFF_BL + so, g_Wl + boff);
    }
}

__global__ void __launch_bounds__(NTHR)
gemm_hmma_kernel(const float* __restrict__ bias, float* __restrict__ out) {
    extern __shared__ __align__(16) char smem[];
    const uint32_t sbase = smem_u32(smem);
    const int tid  = threadIdx.x;
    const int warp = tid >> 5;           // 0..15
    const int lane = tid & 31;
    const int wm   = warp & 3;           // 0..3 -> m offset wm*16
    const int wn   = warp >> 2;          // 0..3 -> n offset wn*16
    const int r0   = blockIdx.y * GBM;
    const int c0   = blockIdx.x * GBN;

    const int mat = lane >> 3, mr = lane & 7;
    const uint32_t aOff =
        (uint32_t)((wm * 16 + (mat & 1) * 8 + mr) * ROWB + (mat >> 1) * 16);
    const int bk  = lane & 15;
    const int bn8 = lane >> 4;
    const uint32_t bOff = (uint32_t)(bk * ROWB + (wn * 16 + bn8 * 8) * 2);

    float acc[2][4];
#pragma unroll
    for (int i = 0; i < 2; i++)
#pragma unroll
        for (int j = 0; j < 4; j++) acc[i][j] = 0.f;

    issue_stage(sbase, 0, 0, r0, c0, tid);
    asm volatile("cp.async.commit_group;" ::: "memory");

    for (int s = 0; s < NSTAGE; s++) {
        const int buf = s & 1;
        if (s + 1 < NSTAGE) {
            issue_stage(sbase, buf ^ 1, s + 1, r0, c0, tid);
            asm volatile("cp.async.commit_group;" ::: "memory");
            asm volatile("cp.async.wait_group 1;" ::: "memory");
        } else {
            asm volatile("cp.async.wait_group 0;" ::: "memory");
        }
        __syncthreads();

        const uint32_t bb = sbase + (uint32_t)buf * BUFSZ;
        const uint32_t aHb = bb + OFF_AH + aOff;
        const uint32_t aLb = bb + OFF_AL + aOff;
        const uint32_t bHb = bb + OFF_BH + bOff;
        const uint32_t bLb = bb + OFF_BL + bOff;

#pragma unroll
        for (int ks = 0; ks < 4; ks++) {
            const uint32_t kByte = (uint32_t)(ks * 16 * ROWB);
            uint32_t ah[4], al[4], bh[4], bl[4];
            ldm_x4(ah, aHb + ks * 32);
            ldm_x4(al, aLb + ks * 32);
            ldm_x4_t(bh, bHb + kByte);
            ldm_x4_t(bl, bLb + kByte);

            mma_bf16(acc[0], ah, bh[0], bh[1]);
            mma_bf16(acc[1], ah, bh[2], bh[3]);
            mma_bf16(acc[0], ah, bl[0], bl[1]);
            mma_bf16(acc[1], ah, bl[2], bl[3]);
            mma_bf16(acc[0], al, bh[0], bh[1]);
            mma_bf16(acc[1], al, bh[2], bh[3]);
        }
        __syncthreads();
    }

    // epilogue: c-frag: c0:(g,t2) c1:(g,t2+1) c2:(g+8,t2) c3:(g+8,t2+1)
    const int rA = r0 + wm * 16 + (lane >> 2);
    const int rB = rA + 8;
    const int cBase = c0 + wn * 16 + (lane & 3) * 2;
#pragma unroll
    for (int nb = 0; nb < 2; nb++) {
        int c = cBase + nb * 8;
        if (c < NCLS) {
            float bv = bias[c];
            out[(size_t)rA * NCLS + c] = acc[nb][0] + bv;
            out[(size_t)rB * NCLS + c] = acc[nb][2] + bv;
        }
        if (c + 1 < NCLS) {
            float bv = bias[c + 1];
            out[(size_t)rA * NCLS + c + 1] = acc[nb][1] + bv;
            out[(size_t)rB * NCLS + c + 1] = acc[nb][3] + bv;
        }
    }
}

// ============================================================================
extern "C" void kernel_launch(void* const* d_in, const int* in_sizes, int n_in,
                              void* d_out, int out_size) {
    const float* x1 = nullptr;
    const float* x2 = nullptr;
    const float* W  = nullptr;
    const float* bb = nullptr;
    for (int i = 0; i < n_in; i++) {
        if (in_sizes[i] == BATCH * NTOK * CDIM) {
            if (!x1) x1 = (const float*)d_in[i];
            else if (!x2) x2 = (const float*)d_in[i];
        } else if (in_sizes[i] == CDIM * NCLS) {
            W = (const float*)d_in[i];
        } else if (in_sizes[i] == NCLS) {
            bb = (const float*)d_in[i];
        }
    }
    float* out = (float*)d_out;

    dim3 g1(BATCH, 3);               // y=0,1: sgm; y=2: W split (overlapped)
    sgm_kernel<<<g1, 256>>>(x1, x2, W);

    static bool attr_done = false;
    if (!attr_done) {
        cudaFuncSetAttribute(gemm_hmma_kernel,
                             cudaFuncAttributeMaxDynamicSharedMemorySize, SMEM_TOTAL);
        attr_done = true;
    }
    dim3 g2(NPAD / GBN, (4 * BATCH) / GBM);   // 11 x 16 = 176
    gemm_hmma_kernel<<<g2, NTHR, SMEM_TOTAL>>>(bb, out);
}

// round 12
// speedup vs baseline: 1.0298x; 1.0298x over previous
#include <cuda_runtime.h>
#include <cuda_bf16.h>
#include <math.h>
#include <stdint.h>

#define NTOK   196
#define CDIM   768
#define BATCH  256
#define NCLS   701
#define NPAD   704      // NCLS padded to 64-multiple

// bf16 hi/lo pre-split operands (device scratch; no allocation)
__device__ __nv_bfloat16 g_Ah[4 * BATCH * CDIM];   // [1024][768]
__device__ __nv_bfloat16 g_Al[4 * BATCH * CDIM];
__device__ __nv_bfloat16 g_Wh[CDIM * NPAD];        // [768][704]
__device__ __nv_bfloat16 g_Wl[CDIM * NPAD];

__device__ __forceinline__ uint32_t smem_u32(const void* p) {
    uint32_t a;
    asm("{ .reg .u64 t; cvta.to.shared.u64 t, %1; cvt.u32.u64 %0, t; }"
        : "=r"(a) : "l"(p));
    return a;
}
__device__ __forceinline__ void split2(float f0, float f1,
                                       uint32_t& hi2, uint32_t& lo2) {
    __nv_bfloat16 h0 = __float2bfloat16(f0);
    __nv_bfloat16 h1 = __float2bfloat16(f1);
    __nv_bfloat16 l0 = __float2bfloat16(f0 - __bfloat162float(h0));
    __nv_bfloat16 l1 = __float2bfloat16(f1 - __bfloat162float(h1));
    __nv_bfloat162 h = __halves2bfloat162(h0, h1);
    __nv_bfloat162 l = __halves2bfloat162(l0, l1);
    hi2 = *reinterpret_cast<uint32_t*>(&h);
    lo2 = *reinterpret_cast<uint32_t*>(&l);
}

// ============================================================================
// Kernel 1: fused SGM per (tensor, sample)  [gridDim.y == 0,1]
//           + W hi/lo split                 [gridDim.y == 2]
// (R9 version — measured ~61us)
// ============================================================================
__global__ void __launch_bounds__(256)
sgm_kernel(const float* __restrict__ x1, const float* __restrict__ x2,
           const float* __restrict__ W) {
    const int tid  = threadIdx.x;

    if (blockIdx.y == 2) {
        const int tot = CDIM * NPAD;
        for (int idx = blockIdx.x * 256 + tid; idx < tot; idx += BATCH * 256) {
            int k = idx / NPAD;
            int n = idx - k * NPAD;
            float v = (n < NCLS) ? W[(size_t)k * NCLS + n] : 0.f;
            __nv_bfloat16 h = __float2bfloat16(v);
            g_Wh[idx] = h;
            g_Wl[idx] = __float2bfloat16(v - __bfloat162float(h));
        }
        return;
    }

    const int b      = blockIdx.x;
    const int tensor = blockIdx.y;
    const float* x = (tensor == 0 ? x1 : x2) + (size_t)b * NTOK * CDIM;

    __shared__ float sT[8][CDIM];
    __shared__ float sTtot[CDIM];
    __shared__ float sM[NTOK];
    __shared__ float sSorted[NTOK];
    __shared__ float sVal[256];
    __shared__ float sMax[256];
    __shared__ int   sIdx[256];
    __shared__ int   sList[112];
    __shared__ int   sCnt;
    __shared__ float sMnMx[2];

    const int warp = tid >> 5;
    const int lane = tid & 31;

    float tacc[24];
#pragma unroll
    for (int i = 0; i < 24; i++) tacc[i] = 0.f;

    int n = warp;
    for (; n + 8 < NTOK; n += 16) {
        const float4* rowA = reinterpret_cast<const float4*>(x + (size_t)n * CDIM);
        const float4* rowB = reinterpret_cast<const float4*>(x + (size_t)(n + 8) * CDIM);
        float msA = 0.f, msB = 0.f;
#pragma unroll
        for (int i = 0; i < 6; i++) {
            float4 va = rowA[lane + 32 * i];
            float4 vb = rowB[lane + 32 * i];
            tacc[4*i+0] += va.x + vb.x; tacc[4*i+1] += va.y + vb.y;
            tacc[4*i+2] += va.z + vb.z; tacc[4*i+3] += va.w + vb.w;
            msA += (va.x + va.y) + (va.z + va.w);
            msB += (vb.x + vb.y) + (vb.z + vb.w);
        }
#pragma unroll
        for (int off = 16; off > 0; off >>= 1) {
            msA += __shfl_down_sync(0xffffffffu, msA, off);
            msB += __shfl_down_sync(0xffffffffu, msB, off);
        }
        if (lane == 0) { sM[n] = msA; sM[n + 8] = msB; }
    }
    if (n < NTOK) {
        const float4* row = reinterpret_cast<const float4*>(x + (size_t)n * CDIM);
        float msum = 0.f;
#pragma unroll
        for (int i = 0; i < 6; i++) {
            float4 v = row[lane + 32 * i];
            tacc[4*i+0] += v.x; tacc[4*i+1] += v.y;
            tacc[4*i+2] += v.z; tacc[4*i+3] += v.w;
            msum += (v.x + v.y) + (v.z + v.w);
        }
#pragma unroll
        for (int off = 16; off > 0; off >>= 1)
            msum += __shfl_down_sync(0xffffffffu, msum, off);
        if (lane == 0) sM[n] = msum;
    }
    {
        float4* st = reinterpret_cast<float4*>(&sT[warp][0]);
#pragma unroll
        for (int i = 0; i < 6; i++)
            st[lane + 32 * i] = make_float4(tacc[4*i], tacc[4*i+1], tacc[4*i+2], tacc[4*i+3]);
    }
    if (tid == 0) sCnt = 0;
    __syncthreads();

    if (tid < 192) {
        float4 t = make_float4(0.f, 0.f, 0.f, 0.f);
#pragma unroll
        for (int w = 0; w < 8; w++) {
            float4 v = reinterpret_cast<float4*>(&sT[w][0])[tid];
            t.x += v.x; t.y += v.y; t.z += v.z; t.w += v.w;
        }
        reinterpret_cast<float4*>(sTtot)[tid] = t;
    }
    __syncthreads();

    sVal[tid] = (tid < NTOK) ? sM[tid] : 3.4e38f;
    sMax[tid] = (tid < NTOK) ? sM[tid] : -3.4e38f;
    __syncthreads();
    for (int s = 128; s > 0; s >>= 1) {
        if (tid < s) {
            sVal[tid] = fminf(sVal[tid], sVal[tid + s]);
            sMax[tid] = fmaxf(sMax[tid], sMax[tid + s]);
        }
        __syncthreads();
    }
    if (tid == 0) { sMnMx[0] = sVal[0]; sMnMx[1] = sMax[0]; }
    __syncthreads();

    const float mn  = sMnMx[0];
    const float mx  = sMnMx[1];
    const float inv = 1.f / (mx - mn);

    float myMn = 0.f;
    if (tid < NTOK) myMn = (sM[tid] - mn) * inv;
    sVal[tid] = myMn;
    __syncthreads();

    int myrank = 0;
    if (tid < NTOK) {
        int r = 0;
#pragma unroll 4
        for (int m = 0; m < NTOK; m++) {
            float o = sVal[m];
            r += (o < myMn) || (o == myMn && m < tid);
        }
        myrank = r;
        sSorted[r] = myMn;
    }
    __syncthreads();

    float dv = -1.f;
    if (tid < NTOK - 1) {
        float s0 = sSorted[tid];
        dv = (s0 == 0.f) ? 0.f : (sSorted[tid + 1] - s0);
    }
    sVal[tid] = dv;
    sIdx[tid] = tid;
    __syncthreads();
    for (int s = 128; s > 0; s >>= 1) {
        if (tid < s) {
            float v2 = sVal[tid + s]; int i2 = sIdx[tid + s];
            if (v2 > sVal[tid] || (v2 == sVal[tid] && i2 < sIdx[tid])) {
                sVal[tid] = v2; sIdx[tid] = i2;
            }
        }
        __syncthreads();
    }
    const int  k         = sIdx[0];
    const bool smallIsFg = (k <= NTOK / 2);

    if (tid < NTOK) {
        bool inSmall = smallIsFg ? (myrank < k) : (myrank >= k);
        if (inSmall) {
            int p = atomicAdd(&sCnt, 1);
            sList[p] = tid;
        }
    }
    __syncthreads();
    const int cnt = sCnt;

#pragma unroll
    for (int i = 0; i < 24; i++) tacc[i] = 0.f;
    for (int j = warp; j < cnt; j += 8) {
        int nn = sList[j];
        const float4* row = reinterpret_cast<const float4*>(x + (size_t)nn * CDIM);
#pragma unroll
        for (int i = 0; i < 6; i++) {
            float4 v = row[lane + 32 * i];
            tacc[4*i+0] += v.x; tacc[4*i+1] += v.y;
            tacc[4*i+2] += v.z; tacc[4*i+3] += v.w;
        }
    }
    {
        float4* st = reinterpret_cast<float4*>(&sT[warp][0]);
#pragma unroll
        for (int i = 0; i < 6; i++)
            st[lane + 32 * i] = make_float4(tacc[4*i], tacc[4*i+1], tacc[4*i+2], tacc[4*i+3]);
    }
    __syncthreads();

    if (tid < 192) {
        float4 S = make_float4(0.f, 0.f, 0.f, 0.f);
#pragma unroll
        for (int w = 0; w < 8; w++) {
            float4 v = reinterpret_cast<float4*>(&sT[w][0])[tid];
            S.x += v.x; S.y += v.y; S.z += v.z; S.w += v.w;
        }
        float4 T = reinterpret_cast<float4*>(sTtot)[tid];

        float4 fgs, bgs;
        if (smallIsFg) {
            fgs = S;
            bgs = make_float4(T.x - S.x, T.y - S.y, T.z - S.z, T.w - S.w);
        } else {
            bgs = S;
            fgs = make_float4(T.x - S.x, T.y - S.y, T.z - S.z, T.w - S.w);
        }
        const float fgc = fmaxf((float)k, 1.f);
        const float bgc = fmaxf((float)(NTOK - k), 1.f);
        float4 fg = make_float4(fgs.x / fgc, fgs.y / fgc, fgs.z / fgc, fgs.w / fgc);
        float4 bg = make_float4(bgs.x / bgc, bgs.y / bgc, bgs.z / bgc, bgs.w / bgc);

        const size_t rowBg = (size_t)((tensor * 2 + 0) * BATCH + b) * CDIM + tid * 4;
        const size_t rowFg = (size_t)((tensor * 2 + 1) * BATCH + b) * CDIM + tid * 4;
        uint32_t h01, l01, h23, l23;
        split2(bg.x, bg.y, h01, l01);
        split2(bg.z, bg.w, h23, l23);
        *reinterpret_cast<uint2*>(&g_Ah[rowBg]) = make_uint2(h01, h23);
        *reinterpret_cast<uint2*>(&g_Al[rowBg]) = make_uint2(l01, l23);
        split2(fg.x, fg.y, h01, l01);
        split2(fg.z, fg.w, h23, l23);
        *reinterpret_cast<uint2*>(&g_Ah[rowFg]) = make_uint2(h01, h23);
        *reinterpret_cast<uint2*>(&g_Al[rowFg]) = make_uint2(l01, l23);
    }
}

// ============================================================================
// Kernel 2: HMMA GEMM, tile 32x64, 256 threads (2x4 warps, warp tile 16x16),
// BK=64. 3-buffer cp.async ring, depth-2 in flight, ONE __syncthreads/stage.
// Grid 11 x 32 = 352 blocks.
// ============================================================================
#define GBM 32
#define GBN 64
#define GBK 64
#define NBUF 3
#define PITCH 72
#define ROWB (PITCH * 2)         // 144
#define NSTAGE (CDIM / GBK)      // 12
#define OFF_AH 0                 // 32 rows * 144 = 4608
#define OFF_AL 4608
#define OFF_BH 9216              // 64 rows * 144 = 9216
#define OFF_BL 18432
#define BUFSZ  27648
#define SMEM_TOTAL (NBUF * BUFSZ)   // 82944

__device__ __forceinline__ void cp16(uint32_t dst, const void* src) {
    asm volatile("cp.async.cg.shared.global [%0], [%1], 16;" :: "r"(dst), "l"(src));
}
__device__ __forceinline__ void ldm_x4(uint32_t r[4], uint32_t addr) {
    asm volatile("ldmatrix.sync.aligned.m8n8.x4.shared.b16 {%0,%1,%2,%3}, [%4];"
                 : "=r"(r[0]), "=r"(r[1]), "=r"(r[2]), "=r"(r[3]) : "r"(addr));
}
__device__ __forceinline__ void ldm_x4_t(uint32_t r[4], uint32_t addr) {
    asm volatile("ldmatrix.sync.aligned.m8n8.x4.trans.shared.b16 {%0,%1,%2,%3}, [%4];"
                 : "=r"(r[0]), "=r"(r[1]), "=r"(r[2]), "=r"(r[3]) : "r"(addr));
}
__device__ __forceinline__ void mma_bf16(float c[4], const uint32_t a[4],
                                         uint32_t b0, uint32_t b1) {
    asm volatile(
        "mma.sync.aligned.m16n8k16.row.col.f32.bf16.bf16.f32 "
        "{%0,%1,%2,%3}, {%4,%5,%6,%7}, {%8,%9}, {%0,%1,%2,%3};"
        : "+f"(c[0]), "+f"(c[1]), "+f"(c[2]), "+f"(c[3])
        : "r"(a[0]), "r"(a[1]), "r"(a[2]), "r"(a[3]), "r"(b0), "r"(b1));
}

__device__ __forceinline__ void issue_stage(uint32_t sbase, int buf, int s,
                                            int r0, int c0, int tid) {
    const int k0 = s * GBK;
    const uint32_t base = sbase + (uint32_t)buf * BUFSZ;
    // A: 32 rows x 8 chunks = 256 cp16 per array -> 1/thread each
    {
        int m  = tid >> 3;               // 0..31
        int ch = tid & 7;
        uint32_t so = (uint32_t)(m * ROWB + ch * 16);
        const size_t aoff = (size_t)(r0 + m) * CDIM + k0 + ch * 8;
        cp16(base + OFF_AH + so, g_Ah + aoff);
        cp16(base + OFF_AL + so, g_Al + aoff);
    }
    // B: 64 k-rows x 8 chunks = 512 cp16 per array -> 2/thread each
#pragma unroll
    for (int i = 0; i < 2; i++) {
        int c  = tid + i * 256;          // 0..511
        int kk = c >> 3;                 // 0..63
        int ch = c & 7;
        uint32_t so = (uint32_t)(kk * ROWB + ch * 16);
        const size_t boff = (size_t)(k0 + kk) * NPAD + c0 + ch * 8;
        cp16(base + OFF_BH + so, g_Wh + boff);
        cp16(base + OFF_BL + so, g_Wl + boff);
    }
}

__global__ void __launch_bounds__(256)
gemm_hmma_kernel(const float* __restrict__ bias, float* __restrict__ out) {
    extern __shared__ __align__(16) char smem[];
    const uint32_t sbase = smem_u32(smem);
    const int tid  = threadIdx.x;
    const int warp = tid >> 5;
    const int lane = tid & 31;
    const int wm   = warp & 1;           // 0..1 -> m offset wm*16
    const int wn   = warp >> 1;          // 0..3 -> n offset wn*16
    const int r0   = blockIdx.y * GBM;
    const int c0   = blockIdx.x * GBN;

    const int mat = lane >> 3, mr = lane & 7;
    const uint32_t aOff =
        (uint32_t)((wm * 16 + (mat & 1) * 8 + mr) * ROWB + (mat >> 1) * 16);
    const int bk  = lane & 15;
    const int bn8 = lane >> 4;
    const uint32_t bOff = (uint32_t)(bk * ROWB + (wn * 16 + bn8 * 8) * 2);

    float acc[2][4];
#pragma unroll
    for (int i = 0; i < 2; i++)
#pragma unroll
        for (int j = 0; j < 4; j++) acc[i][j] = 0.f;

    // prologue: two stages in flight
    issue_stage(sbase, 0, 0, r0, c0, tid);
    asm volatile("cp.async.commit_group;" ::: "memory");
    issue_stage(sbase, 1, 1, r0, c0, tid);
    asm volatile("cp.async.commit_group;" ::: "memory");

    for (int s = 0; s < NSTAGE; s++) {
        // wait for stage s data (pending <= 1 leaves stage s+1 in flight)
        if (s == NSTAGE - 1) {
            asm volatile("cp.async.wait_group 0;" ::: "memory");
        } else {
            asm volatile("cp.async.wait_group 1;" ::: "memory");
        }
        __syncthreads();   // all warps done reading stage s-1's buffer

        // issue s+2 into buf (s+2)%3 == (s-1)%3 — safe after the barrier
        if (s + 2 < NSTAGE) {
            issue_stage(sbase, (s + 2) % NBUF, s + 2, r0, c0, tid);
            asm volatile("cp.async.commit_group;" ::: "memory");
        }

        const uint32_t bb = sbase + (uint32_t)(s % NBUF) * BUFSZ;
        const uint32_t aHb = bb + OFF_AH + aOff;
        const uint32_t aLb = bb + OFF_AL + aOff;
        const uint32_t bHb = bb + OFF_BH + bOff;
        const uint32_t bLb = bb + OFF_BL + bOff;

#pragma unroll
        for (int ks = 0; ks < 4; ks++) {
            const uint32_t kByte = (uint32_t)(ks * 16 * ROWB);
            uint32_t ah[4], al[4], bh[4], bl[4];
            ldm_x4(ah, aHb + ks * 32);
            ldm_x4(al, aLb + ks * 32);
            ldm_x4_t(bh, bHb + kByte);
            ldm_x4_t(bl, bLb + kByte);

            mma_bf16(acc[0], ah, bh[0], bh[1]);
            mma_bf16(acc[1], ah, bh[2], bh[3]);
            mma_bf16(acc[0], ah, bl[0], bl[1]);
            mma_bf16(acc[1], ah, bl[2], bl[3]);
            mma_bf16(acc[0], al, bh[0], bh[1]);
            mma_bf16(acc[1], al, bh[2], bh[3]);
        }
    }

    // epilogue: c-frag: c0:(g,t2) c1:(g,t2+1) c2:(g+8,t2) c3:(g+8,t2+1)
    const int rA = r0 + wm * 16 + (lane >> 2);
    const int rB = rA + 8;
    const int cBase = c0 + wn * 16 + (lane & 3) * 2;
#pragma unroll
    for (int nb = 0; nb < 2; nb++) {
        int c = cBase + nb * 8;
        if (c < NCLS) {
            float bv = bias[c];
            out[(size_t)rA * NCLS + c] = acc[nb][0] + bv;
            out[(size_t)rB * NCLS + c] = acc[nb][2] + bv;
        }
        if (c + 1 < NCLS) {
            float bv = bias[c + 1];
            out[(size_t)rA * NCLS + c + 1] = acc[nb][1] + bv;
            out[(size_t)rB * NCLS + c + 1] = acc[nb][3] + bv;
        }
    }
}

// ============================================================================
extern "C" void kernel_launch(void* const* d_in, const int* in_sizes, int n_in,
                              void* d_out, int out_size) {
    const float* x1 = nullptr;
    const float* x2 = nullptr;
    const float* W  = nullptr;
    const float* bb = nullptr;
    for (int i = 0; i < n_in; i++) {
        if (in_sizes[i] == BATCH * NTOK * CDIM) {
            if (!x1) x1 = (const float*)d_in[i];
            else if (!x2) x2 = (const float*)d_in[i];
        } else if (in_sizes[i] == CDIM * NCLS) {
            W = (const float*)d_in[i];
        } else if (in_sizes[i] == NCLS) {
            bb = (const float*)d_in[i];
        }
    }
    float* out = (float*)d_out;

    dim3 g1(BATCH, 3);               // y=0,1: sgm; y=2: W split (overlapped)
    sgm_kernel<<<g1, 256>>>(x1, x2, W);

    static bool attr_done = false;
    if (!attr_done) {
        cudaFuncSetAttribute(gemm_hmma_kernel,
                             cudaFuncAttributeMaxDynamicSharedMemorySize, SMEM_TOTAL);
        attr_done = true;
    }
    dim3 g2(NPAD / GBN, (4 * BATCH) / GBM);   // 11 x 32 = 352
    gemm_hmma_kernel<<<g2, 256, SMEM_TOTAL>>>(bb, out);
}

// round 13
// speedup vs baseline: 1.0332x; 1.0034x over previous
#include <cuda_runtime.h>
#include <cuda_bf16.h>
#include <math.h>
#include <stdint.h>

#define NTOK   196
#define CDIM   768
#define BATCH  256
#define NCLS   701
#define NPAD   704      // NCLS padded to 64-multiple

// bf16 hi/lo pre-split operands (device scratch; no allocation)
__device__ __nv_bfloat16 g_Ah[4 * BATCH * CDIM];   // [1024][768]
__device__ __nv_bfloat16 g_Al[4 * BATCH * CDIM];
__device__ __nv_bfloat16 g_Wh[CDIM * NPAD];        // [768][704]
__device__ __nv_bfloat16 g_Wl[CDIM * NPAD];

__device__ __forceinline__ uint32_t smem_u32(const void* p) {
    uint32_t a;
    asm("{ .reg .u64 t; cvta.to.shared.u64 t, %1; cvt.u32.u64 %0, t; }"
        : "=r"(a) : "l"(p));
    return a;
}
__device__ __forceinline__ void split2(float f0, float f1,
                                       uint32_t& hi2, uint32_t& lo2) {
    __nv_bfloat16 h0 = __float2bfloat16(f0);
    __nv_bfloat16 h1 = __float2bfloat16(f1);
    __nv_bfloat16 l0 = __float2bfloat16(f0 - __bfloat162float(h0));
    __nv_bfloat16 l1 = __float2bfloat16(f1 - __bfloat162float(h1));
    __nv_bfloat162 h = __halves2bfloat162(h0, h1);
    __nv_bfloat162 l = __halves2bfloat162(l0, l1);
    hi2 = *reinterpret_cast<uint32_t*>(&h);
    lo2 = *reinterpret_cast<uint32_t*>(&l);
}

// ============================================================================
// Kernel 1: fused SGM per (tensor, sample)  [gridDim.y == 0,1]
//           + W hi/lo split                 [gridDim.y == 2]
// (R9 version — measured ~61us)
// ============================================================================
__global__ void __launch_bounds__(256)
sgm_kernel(const float* __restrict__ x1, const float* __restrict__ x2,
           const float* __restrict__ W) {
    const int tid  = threadIdx.x;

    if (blockIdx.y == 2) {
        const int tot = CDIM * NPAD;
        for (int idx = blockIdx.x * 256 + tid; idx < tot; idx += BATCH * 256) {
            int k = idx / NPAD;
            int n = idx - k * NPAD;
            float v = (n < NCLS) ? W[(size_t)k * NCLS + n] : 0.f;
            __nv_bfloat16 h = __float2bfloat16(v);
            g_Wh[idx] = h;
            g_Wl[idx] = __float2bfloat16(v - __bfloat162float(h));
        }
        return;
    }

    const int b      = blockIdx.x;
    const int tensor = blockIdx.y;
    const float* x = (tensor == 0 ? x1 : x2) + (size_t)b * NTOK * CDIM;

    __shared__ float sT[8][CDIM];
    __shared__ float sTtot[CDIM];
    __shared__ float sM[NTOK];
    __shared__ float sSorted[NTOK];
    __shared__ float sVal[256];
    __shared__ float sMax[256];
    __shared__ int   sIdx[256];
    __shared__ int   sList[112];
    __shared__ int   sCnt;
    __shared__ float sMnMx[2];

    const int warp = tid >> 5;
    const int lane = tid & 31;

    float tacc[24];
#pragma unroll
    for (int i = 0; i < 24; i++) tacc[i] = 0.f;

    int n = warp;
    for (; n + 8 < NTOK; n += 16) {
        const float4* rowA = reinterpret_cast<const float4*>(x + (size_t)n * CDIM);
        const float4* rowB = reinterpret_cast<const float4*>(x + (size_t)(n + 8) * CDIM);
        float msA = 0.f, msB = 0.f;
#pragma unroll
        for (int i = 0; i < 6; i++) {
            float4 va = rowA[lane + 32 * i];
            float4 vb = rowB[lane + 32 * i];
            tacc[4*i+0] += va.x + vb.x; tacc[4*i+1] += va.y + vb.y;
            tacc[4*i+2] += va.z + vb.z; tacc[4*i+3] += va.w + vb.w;
            msA += (va.x + va.y) + (va.z + va.w);
            msB += (vb.x + vb.y) + (vb.z + vb.w);
        }
#pragma unroll
        for (int off = 16; off > 0; off >>= 1) {
            msA += __shfl_down_sync(0xffffffffu, msA, off);
            msB += __shfl_down_sync(0xffffffffu, msB, off);
        }
        if (lane == 0) { sM[n] = msA; sM[n + 8] = msB; }
    }
    if (n < NTOK) {
        const float4* row = reinterpret_cast<const float4*>(x + (size_t)n * CDIM);
        float msum = 0.f;
#pragma unroll
        for (int i = 0; i < 6; i++) {
            float4 v = row[lane + 32 * i];
            tacc[4*i+0] += v.x; tacc[4*i+1] += v.y;
            tacc[4*i+2] += v.z; tacc[4*i+3] += v.w;
            msum += (v.x + v.y) + (v.z + v.w);
        }
#pragma unroll
        for (int off = 16; off > 0; off >>= 1)
            msum += __shfl_down_sync(0xffffffffu, msum, off);
        if (lane == 0) sM[n] = msum;
    }
    {
        float4* st = reinterpret_cast<float4*>(&sT[warp][0]);
#pragma unroll
        for (int i = 0; i < 6; i++)
            st[lane + 32 * i] = make_float4(tacc[4*i], tacc[4*i+1], tacc[4*i+2], tacc[4*i+3]);
    }
    if (tid == 0) sCnt = 0;
    __syncthreads();

    if (tid < 192) {
        float4 t = make_float4(0.f, 0.f, 0.f, 0.f);
#pragma unroll
        for (int w = 0; w < 8; w++) {
            float4 v = reinterpret_cast<float4*>(&sT[w][0])[tid];
            t.x += v.x; t.y += v.y; t.z += v.z; t.w += v.w;
        }
        reinterpret_cast<float4*>(sTtot)[tid] = t;
    }
    __syncthreads();

    sVal[tid] = (tid < NTOK) ? sM[tid] : 3.4e38f;
    sMax[tid] = (tid < NTOK) ? sM[tid] : -3.4e38f;
    __syncthreads();
    for (int s = 128; s > 0; s >>= 1) {
        if (tid < s) {
            sVal[tid] = fminf(sVal[tid], sVal[tid + s]);
            sMax[tid] = fmaxf(sMax[tid], sMax[tid + s]);
        }
        __syncthreads();
    }
    if (tid == 0) { sMnMx[0] = sVal[0]; sMnMx[1] = sMax[0]; }
    __syncthreads();

    const float mn  = sMnMx[0];
    const float mx  = sMnMx[1];
    const float inv = 1.f / (mx - mn);

    float myMn = 0.f;
    if (tid < NTOK) myMn = (sM[tid] - mn) * inv;
    sVal[tid] = myMn;
    __syncthreads();

    int myrank = 0;
    if (tid < NTOK) {
        int r = 0;
#pragma unroll 4
        for (int m = 0; m < NTOK; m++) {
            float o = sVal[m];
            r += (o < myMn) || (o == myMn && m < tid);
        }
        myrank = r;
        sSorted[r] = myMn;
    }
    __syncthreads();

    float dv = -1.f;
    if (tid < NTOK - 1) {
        float s0 = sSorted[tid];
        dv = (s0 == 0.f) ? 0.f : (sSorted[tid + 1] - s0);
    }
    sVal[tid] = dv;
    sIdx[tid] = tid;
    __syncthreads();
    for (int s = 128; s > 0; s >>= 1) {
        if (tid < s) {
            float v2 = sVal[tid + s]; int i2 = sIdx[tid + s];
            if (v2 > sVal[tid] || (v2 == sVal[tid] && i2 < sIdx[tid])) {
                sVal[tid] = v2; sIdx[tid] = i2;
            }
        }
        __syncthreads();
    }
    const int  k         = sIdx[0];
    const bool smallIsFg = (k <= NTOK / 2);

    if (tid < NTOK) {
        bool inSmall = smallIsFg ? (myrank < k) : (myrank >= k);
        if (inSmall) {
            int p = atomicAdd(&sCnt, 1);
            sList[p] = tid;
        }
    }
    __syncthreads();
    const int cnt = sCnt;

#pragma unroll
    for (int i = 0; i < 24; i++) tacc[i] = 0.f;
    for (int j = warp; j < cnt; j += 8) {
        int nn = sList[j];
        const float4* row = reinterpret_cast<const float4*>(x + (size_t)nn * CDIM);
#pragma unroll
        for (int i = 0; i < 6; i++) {
            float4 v = row[lane + 32 * i];
            tacc[4*i+0] += v.x; tacc[4*i+1] += v.y;
            tacc[4*i+2] += v.z; tacc[4*i+3] += v.w;
        }
    }
    {
        float4* st = reinterpret_cast<float4*>(&sT[warp][0]);
#pragma unroll
        for (int i = 0; i < 6; i++)
            st[lane + 32 * i] = make_float4(tacc[4*i], tacc[4*i+1], tacc[4*i+2], tacc[4*i+3]);
    }
    __syncthreads();

    if (tid < 192) {
        float4 S = make_float4(0.f, 0.f, 0.f, 0.f);
#pragma unroll
        for (int w = 0; w < 8; w++) {
            float4 v = reinterpret_cast<float4*>(&sT[w][0])[tid];
            S.x += v.x; S.y += v.y; S.z += v.z; S.w += v.w;
        }
        float4 T = reinterpret_cast<float4*>(sTtot)[tid];

        float4 fgs, bgs;
        if (smallIsFg) {
            fgs = S;
            bgs = make_float4(T.x - S.x, T.y - S.y, T.z - S.z, T.w - S.w);
        } else {
            bgs = S;
            fgs = make_float4(T.x - S.x, T.y - S.y, T.z - S.z, T.w - S.w);
        }
        const float fgc = fmaxf((float)k, 1.f);
        const float bgc = fmaxf((float)(NTOK - k), 1.f);
        float4 fg = make_float4(fgs.x / fgc, fgs.y / fgc, fgs.z / fgc, fgs.w / fgc);
        float4 bg = make_float4(bgs.x / bgc, bgs.y / bgc, bgs.z / bgc, bgs.w / bgc);

        const size_t rowBg = (size_t)((tensor * 2 + 0) * BATCH + b) * CDIM + tid * 4;
        const size_t rowFg = (size_t)((tensor * 2 + 1) * BATCH + b) * CDIM + tid * 4;
        uint32_t h01, l01, h23, l23;
        split2(bg.x, bg.y, h01, l01);
        split2(bg.z, bg.w, h23, l23);
        *reinterpret_cast<uint2*>(&g_Ah[rowBg]) = make_uint2(h01, h23);
        *reinterpret_cast<uint2*>(&g_Al[rowBg]) = make_uint2(l01, l23);
        split2(fg.x, fg.y, h01, l01);
        split2(fg.z, fg.w, h23, l23);
        *reinterpret_cast<uint2*>(&g_Ah[rowFg]) = make_uint2(h01, h23);
        *reinterpret_cast<uint2*>(&g_Al[rowFg]) = make_uint2(l01, l23);
    }
}

// ============================================================================
// Kernel 2: HMMA GEMM, tile 32x64, 256 threads (2x4 warps, warp tile 16x16),
// BK=64, 3-buffer cp.async ring, ONE sync/stage.
// SPLIT ACCUMULATORS: one fp32 accumulator set per bf16 split term (6
// independent HMMA dependency chains instead of 2); summed in epilogue.
// ============================================================================
#define GBM 32
#define GBN 64
#define GBK 64
#define NBUF 3
#define PITCH 72
#define ROWB (PITCH * 2)         // 144
#define NSTAGE (CDIM / GBK)      // 12
#define OFF_AH 0                 // 32 rows * 144 = 4608
#define OFF_AL 4608
#define OFF_BH 9216              // 64 rows * 144 = 9216
#define OFF_BL 18432
#define BUFSZ  27648
#define SMEM_TOTAL (NBUF * BUFSZ)   // 82944

__device__ __forceinline__ void cp16(uint32_t dst, const void* src) {
    asm volatile("cp.async.cg.shared.global [%0], [%1], 16;" :: "r"(dst), "l"(src));
}
__device__ __forceinline__ void ldm_x4(uint32_t r[4], uint32_t addr) {
    asm volatile("ldmatrix.sync.aligned.m8n8.x4.shared.b16 {%0,%1,%2,%3}, [%4];"
                 : "=r"(r[0]), "=r"(r[1]), "=r"(r[2]), "=r"(r[3]) : "r"(addr));
}
__device__ __forceinline__ void ldm_x4_t(uint32_t r[4], uint32_t addr) {
    asm volatile("ldmatrix.sync.aligned.m8n8.x4.trans.shared.b16 {%0,%1,%2,%3}, [%4];"
                 : "=r"(r[0]), "=r"(r[1]), "=r"(r[2]), "=r"(r[3]) : "r"(addr));
}
__device__ __forceinline__ void mma_bf16(float c[4], const uint32_t a[4],
                                         uint32_t b0, uint32_t b1) {
    asm volatile(
        "mma.sync.aligned.m16n8k16.row.col.f32.bf16.bf16.f32 "
        "{%0,%1,%2,%3}, {%4,%5,%6,%7}, {%8,%9}, {%0,%1,%2,%3};"
        : "+f"(c[0]), "+f"(c[1]), "+f"(c[2]), "+f"(c[3])
        : "r"(a[0]), "r"(a[1]), "r"(a[2]), "r"(a[3]), "r"(b0), "r"(b1));
}

__device__ __forceinline__ void issue_stage(uint32_t sbase, int buf, int s,
                                            int r0, int c0, int tid) {
    const int k0 = s * GBK;
    const uint32_t base = sbase + (uint32_t)buf * BUFSZ;
    // A: 32 rows x 8 chunks = 256 cp16 per array -> 1/thread each
    {
        int m  = tid >> 3;               // 0..31
        int ch = tid & 7;
        uint32_t so = (uint32_t)(m * ROWB + ch * 16);
        const size_t aoff = (size_t)(r0 + m) * CDIM + k0 + ch * 8;
        cp16(base + OFF_AH + so, g_Ah + aoff);
        cp16(base + OFF_AL + so, g_Al + aoff);
    }
    // B: 64 k-rows x 8 chunks = 512 cp16 per array -> 2/thread each
#pragma unroll
    for (int i = 0; i < 2; i++) {
        int c  = tid + i * 256;          // 0..511
        int kk = c >> 3;                 // 0..63
        int ch = c & 7;
        uint32_t so = (uint32_t)(kk * ROWB + ch * 16);
        const size_t boff = (size_t)(k0 + kk) * NPAD + c0 + ch * 8;
        cp16(base + OFF_BH + so, g_Wh + boff);
        cp16(base + OFF_BL + so, g_Wl + boff);
    }
}

__global__ void __launch_bounds__(256)
gemm_hmma_kernel(const float* __restrict__ bias, float* __restrict__ out) {
    extern __shared__ __align__(16) char smem[];
    const uint32_t sbase = smem_u32(smem);
    const int tid  = threadIdx.x;
    const int warp = tid >> 5;
    const int lane = tid & 31;
    const int wm   = warp & 1;           // 0..1 -> m offset wm*16
    const int wn   = warp >> 1;          // 0..3 -> n offset wn*16
    const int r0   = blockIdx.y * GBM;
    const int c0   = blockIdx.x * GBN;

    const int mat = lane >> 3, mr = lane & 7;
    const uint32_t aOff =
        (uint32_t)((wm * 16 + (mat & 1) * 8 + mr) * ROWB + (mat >> 1) * 16);
    const int bk  = lane & 15;
    const int bn8 = lane >> 4;
    const uint32_t bOff = (uint32_t)(bk * ROWB + (wn * 16 + bn8 * 8) * 2);

    // acc[t][nb][frag]: t = split term (AhBh, AhBl, AlBh) — 6 independent
    // HMMA dependency chains; summed at the end.
    float acc[3][2][4];
#pragma unroll
    for (int t = 0; t < 3; t++)
#pragma unroll
        for (int i = 0; i < 2; i++)
#pragma unroll
            for (int j = 0; j < 4; j++) acc[t][i][j] = 0.f;

    // prologue: two stages in flight
    issue_stage(sbase, 0, 0, r0, c0, tid);
    asm volatile("cp.async.commit_group;" ::: "memory");
    issue_stage(sbase, 1, 1, r0, c0, tid);
    asm volatile("cp.async.commit_group;" ::: "memory");

    for (int s = 0; s < NSTAGE; s++) {
        if (s == NSTAGE - 1) {
            asm volatile("cp.async.wait_group 0;" ::: "memory");
        } else {
            asm volatile("cp.async.wait_group 1;" ::: "memory");
        }
        __syncthreads();   // all warps done reading stage s-1's buffer

        if (s + 2 < NSTAGE) {
            issue_stage(sbase, (s + 2) % NBUF, s + 2, r0, c0, tid);
            asm volatile("cp.async.commit_group;" ::: "memory");
        }

        const uint32_t bb = sbase + (uint32_t)(s % NBUF) * BUFSZ;
        const uint32_t aHb = bb + OFF_AH + aOff;
        const uint32_t aLb = bb + OFF_AL + aOff;
        const uint32_t bHb = bb + OFF_BH + bOff;
        const uint32_t bLb = bb + OFF_BL + bOff;

#pragma unroll
        for (int ks = 0; ks < 4; ks++) {
            const uint32_t kByte = (uint32_t)(ks * 16 * ROWB);
            uint32_t ah[4], al[4], bh[4], bl[4];
            ldm_x4(ah, aHb + ks * 32);
            ldm_x4(al, aLb + ks * 32);
            ldm_x4_t(bh, bHb + kByte);
            ldm_x4_t(bl, bLb + kByte);

            // each chain touched once per ks -> dependent ops 6 apart
            mma_bf16(acc[0][0], ah, bh[0], bh[1]);
            mma_bf16(acc[1][0], ah, bl[0], bl[1]);
            mma_bf16(acc[2][0], al, bh[0], bh[1]);
            mma_bf16(acc[0][1], ah, bh[2], bh[3]);
            mma_bf16(acc[1][1], ah, bl[2], bl[3]);
            mma_bf16(acc[2][1], al, bh[2], bh[3]);
        }
    }

    // epilogue: sum terms; c-frag: c0:(g,t2) c1:(g,t2+1) c2:(g+8,t2) c3:(g+8,t2+1)
    const int rA = r0 + wm * 16 + (lane >> 2);
    const int rB = rA + 8;
    const int cBase = c0 + wn * 16 + (lane & 3) * 2;
#pragma unroll
    for (int nb = 0; nb < 2; nb++) {
        float f0 = acc[0][nb][0] + acc[1][nb][0] + acc[2][nb][0];
        float f1 = acc[0][nb][1] + acc[1][nb][1] + acc[2][nb][1];
        float f2 = acc[0][nb][2] + acc[1][nb][2] + acc[2][nb][2];
        float f3 = acc[0][nb][3] + acc[1][nb][3] + acc[2][nb][3];
        int c = cBase + nb * 8;
        if (c < NCLS) {
            float bv = bias[c];
            out[(size_t)rA * NCLS + c] = f0 + bv;
            out[(size_t)rB * NCLS + c] = f2 + bv;
        }
        if (c + 1 < NCLS) {
            float bv = bias[c + 1];
            out[(size_t)rA * NCLS + c + 1] = f1 + bv;
            out[(size_t)rB * NCLS + c + 1] = f3 + bv;
        }
    }
}

// ============================================================================
extern "C" void kernel_launch(void* const* d_in, const int* in_sizes, int n_in,
                              void* d_out, int out_size) {
    const float* x1 = nullptr;
    const float* x2 = nullptr;
    const float* W  = nullptr;
    const float* bb = nullptr;
    for (int i = 0; i < n_in; i++) {
        if (in_sizes[i] == BATCH * NTOK * CDIM) {
            if (!x1) x1 = (const float*)d_in[i];
            else if (!x2) x2 = (const float*)d_in[i];
        } else if (in_sizes[i] == CDIM * NCLS) {
            W = (const float*)d_in[i];
        } else if (in_sizes[i] == NCLS) {
            bb = (const float*)d_in[i];
        }
    }
    float* out = (float*)d_out;

    dim3 g1(BATCH, 3);               // y=0,1: sgm; y=2: W split (overlapped)
    sgm_kernel<<<g1, 256>>>(x1, x2, W);

    static bool attr_done = false;
    if (!attr_done) {
        cudaFuncSetAttribute(gemm_hmma_kernel,
                             cudaFuncAttributeMaxDynamicSharedMemorySize, SMEM_TOTAL);
        attr_done = true;
    }
    dim3 g2(NPAD / GBN, (4 * BATCH) / GBM);   // 11 x 32 = 352
    gemm_hmma_kernel<<<g2, 256, SMEM_TOTAL>>>(bb, out);
}